// round 10
// baseline (speedup 1.0000x reference)
#include <cuda_runtime.h>
#include <cuda_bf16.h>

#define THREADS 256
#define NWARP   8
#define NBINS   2048     // positive-value histogram, float bits [30:20]
#define BPT     8        // bins per thread
#define CAP     2048     // rank-path candidate cap (overlays hist)

// Scratch: boost factors (n <= 16384 supported; actual n = 4096)
__device__ float g_bf[16384];

__global__ void boost_kernel(const float* __restrict__ duty,
                             const int* __restrict__ kp, int n) {
    int i = blockIdx.x * blockDim.x + threadIdx.x;
    if (i < n) {
        float td = (float)(*kp) / (float)n;
        g_bf[i] = expf(td - duty[i]);   // boostStrength = 1.0
    }
}

// Monotone float -> uint key (fallback path only)
__device__ __forceinline__ unsigned f2key(float f) {
    unsigned u = __float_as_uint(f);
    return u ^ (unsigned)(((int)u >> 31) | 0x80000000);
}
__device__ __forceinline__ float key2f(unsigned k) {
    unsigned m = ((int)k < 0) ? 0x80000000u : 0xFFFFFFFFu;
    return __uint_as_float(k ^ m);
}

struct Sm {
    union {
        unsigned hist[NBINS];   // 8KB, dead after the in-register scan
        unsigned list[CAP];     // candidate overlay (raw positive-float bits)
    } u;
    unsigned wtot[NWARP];
    unsigned sBin, sKr, sCnt, sNum, sThr;
};

template <int EPV>  // float4 elements per thread per row
__global__ __launch_bounds__(THREADS, 4)
void kwinner_kernel(const float* __restrict__ x,
                    const int* __restrict__ kp,
                    float* __restrict__ out, int n) {
    const int row  = blockIdx.x;
    const int t    = threadIdx.x;
    const int lane = t & 31;
    const int wid  = t >> 5;
    const unsigned lmask = (1u << lane) - 1u;
    constexpr int NK = EPV * 4;

    __shared__ Sm s;

    // Zero histogram: two uint4 stores per thread (2048 bins)
    ((uint4*)s.u.hist)[t]           = make_uint4(0, 0, 0, 0);
    ((uint4*)s.u.hist)[t + THREADS] = make_uint4(0, 0, 0, 0);

    const float4* xrow = (const float4*)(x + (size_t)row * n);
    const float4* bfv  = (const float4*)g_bf;

    float4 xv[EPV];     // x stays in registers (exact passthrough output)
    float  b[NK];       // boosted values; raw bits are monotone for positives
    #pragma unroll
    for (int j = 0; j < EPV; j++) {
        int f = t + j * THREADS;
        xv[j] = xrow[f];
        float4 bf = bfv[f];
        b[j*4+0] = xv[j].x * bf.x;
        b[j*4+1] = xv[j].y * bf.y;
        b[j*4+2] = xv[j].z * bf.z;
        b[j*4+3] = xv[j].w * bf.w;
    }
    if (t == 0) { s.sNum = 0; s.sCnt = 0xFFFFFFFFu; }
    __syncthreads();   // hist zeroed

    // Histogram positive values (sign bit clear): bin = float bits [30:20].
    // Plain atomics: spread digits keep conflict degree low (R7 showed
    // match-aggregation loses here).
    #pragma unroll
    for (int e = 0; e < NK; e++) {
        unsigned u = __float_as_uint(b[e]);
        if ((int)u >= 0)                    // positive or +0
            atomicAdd(&s.u.hist[u >> 20], 1u);   // u>>20 in [0,2047]
    }
    __syncthreads();

    const unsigned k0 = (unsigned)__ldg(kp);

    // Suffix-count scan; thread t owns bins [8t, 8t+8), kept in registers
    uint4 a4 = ((const uint4*)s.u.hist)[t * 2];
    uint4 b4 = ((const uint4*)s.u.hist)[t * 2 + 1];
    unsigned hh[BPT] = {a4.x, a4.y, a4.z, a4.w, b4.x, b4.y, b4.z, b4.w};
    unsigned tot = 0;
    #pragma unroll
    for (int i = 0; i < BPT; i++) tot += hh[i];

    unsigned v = tot;   // becomes sum over lanes [lane..31]
    #pragma unroll
    for (int off = 1; off < 32; off <<= 1) {
        unsigned u = __shfl_down_sync(0xFFFFFFFFu, v, off);
        if (lane + off < 32) v += u;
    }
    if (lane == 0) s.wtot[wid] = v;
    __syncthreads();

    unsigned run = v - tot;                 // in-warp suffix above own chunk
    for (int j = wid + 1; j < NWARP; j++)   // higher warps (broadcast reads)
        run += s.wtot[j];
    #pragma unroll
    for (int i = BPT - 1; i >= 0; i--) {
        unsigned nxt = run;      // suffix(bin+1)
        run += hh[i];            // suffix(bin)
        if (run >= k0 && nxt < k0) {   // unique crossing bin
            s.sBin = (unsigned)(t * BPT + i);
            s.sKr  = k0 - nxt;
            s.sCnt = hh[i];
        }
    }
    __syncthreads();
    const unsigned bin = s.sBin;
    const unsigned kr  = s.sKr;
    const unsigned C1  = s.sCnt;   // 0xFFFFFFFF if positives < k0

    float thresh;
    if (C1 <= CAP) {
        // Compact crossing-bin candidates. Warp-aggregated counter bump:
        // all active lanes hit ONE address -> aggregate (opposite of hist).
        #pragma unroll
        for (int e = 0; e < NK; e++) {
            unsigned u   = __float_as_uint(b[e]);
            bool     prd = (u >> 20) == bin;   // negatives can't match (bin<2048 w/ sign 0)
            unsigned bal = __ballot_sync(0xFFFFFFFFu, prd);
            if (bal) {
                int ldr = __ffs(bal) - 1;
                unsigned base = 0;
                if (lane == ldr) base = atomicAdd(&s.sNum, (unsigned)__popc(bal));
                base = __shfl_sync(0xFFFFFFFFu, base, ldr);
                if (prd) s.u.list[base + __popc(bal & lmask)] = u;
            }
        }
        __syncthreads();
        const unsigned C = s.sNum;   // == C1

        // Parallel rank on raw bits (uint order == float order for positives):
        // candidate with (gt < kr <= ge) is the kr-th largest in the bin.
        for (unsigned i = t; i < C; i += THREADS) {
            unsigned ki = s.u.list[i];
            unsigned gt = 0, ge = 0;
            #pragma unroll 4
            for (unsigned j = 0; j < C; j++) {
                unsigned lj = s.u.list[j];
                gt += (lj > ki)  ? 1u : 0u;
                ge += (lj >= ki) ? 1u : 0u;
            }
            if (gt < kr && ge >= kr) s.sThr = ki;   // ties write same value
        }
        __syncthreads();
        thresh = __uint_as_float(s.sThr);
    } else {
        // Exactness fallback (positives < k0): block-wide greedy bit-descent
        // over full monotone keys. Never taken on benchmark data.
        unsigned thr = 0;
        for (int bb = 31; bb >= 0; bb--) {
            unsigned test = thr | (1u << bb);
            unsigned c = 0;
            #pragma unroll
            for (int e = 0; e < NK; e++) c += (f2key(b[e]) >= test) ? 1u : 0u;
            c = __reduce_add_sync(0xFFFFFFFFu, c);
            if (lane == 0) s.wtot[wid] = c;
            __syncthreads();
            unsigned cb = 0;
            #pragma unroll
            for (int j = 0; j < NWARP; j++) cb += s.wtot[j];
            if (cb >= k0) thr = test;
            __syncthreads();
        }
        thresh = key2f(thr);
    }

    // Output: EXACT passthrough of register-resident x; float >= mask
    // (identical semantics to the reference's boosted >= bottom).
    float4* orow = (float4*)(out + (size_t)row * n);
    #pragma unroll
    for (int j = 0; j < EPV; j++) {
        int f = t + j * THREADS;
        float4 o;
        o.x = (b[j*4+0] >= thresh) ? xv[j].x : 0.0f;
        o.y = (b[j*4+1] >= thresh) ? xv[j].y : 0.0f;
        o.z = (b[j*4+2] >= thresh) ? xv[j].z : 0.0f;
        o.w = (b[j*4+3] >= thresh) ? xv[j].w : 0.0f;
        orow[f] = o;
    }
}

extern "C" void kernel_launch(void* const* d_in, const int* in_sizes, int n_in,
                              void* d_out, int out_size) {
    const float* x    = (const float*)d_in[0];
    const float* duty = (const float*)d_in[1];
    const int*   kp   = (const int*)d_in[2];
    float*       out  = (float*)d_out;

    int n    = in_sizes[1];          // 4096
    int rows = in_sizes[0] / n;      // 8192

    boost_kernel<<<(n + 255) / 256, 256>>>(duty, kp, n);

    int epv = n / (THREADS * 4);
    switch (epv) {
        case 1:  kwinner_kernel<1><<<rows, THREADS>>>(x, kp, out, n);  break;
        case 2:  kwinner_kernel<2><<<rows, THREADS>>>(x, kp, out, n);  break;
        case 4:  kwinner_kernel<4><<<rows, THREADS>>>(x, kp, out, n);  break;
        case 8:  kwinner_kernel<8><<<rows, THREADS>>>(x, kp, out, n);  break;
        case 16: kwinner_kernel<16><<<rows, THREADS>>>(x, kp, out, n); break;
        default: break; // unsupported shape (not expected for this problem)
    }
}

// round 12
// speedup vs baseline: 1.0987x; 1.0987x over previous
#include <cuda_runtime.h>
#include <cuda_bf16.h>

#define THREADS 256
#define NWARP   8
#define NBINS   2048     // positive-value histogram, float bits [30:20]
#define BPT     8        // bins per thread
#define CAP     2048     // rank-path candidate cap (overlays hist)

// Scratch: boost factors (n <= 16384 supported; actual n = 4096)
__device__ float g_bf[16384];

__global__ void boost_kernel(const float* __restrict__ duty,
                             const int* __restrict__ kp, int n) {
    int i = blockIdx.x * blockDim.x + threadIdx.x;
    if (i < n) {
        float td = (float)(*kp) / (float)n;
        g_bf[i] = expf(td - duty[i]);   // boostStrength = 1.0
    }
}

// Monotone float -> uint key (fallback path only)
__device__ __forceinline__ unsigned f2key(float f) {
    unsigned u = __float_as_uint(f);
    return u ^ (unsigned)(((int)u >> 31) | 0x80000000);
}
__device__ __forceinline__ float key2f(unsigned k) {
    unsigned m = ((int)k < 0) ? 0x80000000u : 0xFFFFFFFFu;
    return __uint_as_float(k ^ m);
}

struct Sm {
    union {
        unsigned hist[NBINS];   // 8KB, dead after the in-register scan
        unsigned list[CAP];     // candidate overlay (raw positive-float bits)
    } u;
    unsigned wtot[NWARP];
    unsigned sBin, sKr, sCnt, sNum, sThr;
};

template <int EPV>  // float4 elements per thread per row
__global__ __launch_bounds__(THREADS, 4)
void kwinner_kernel(const float* __restrict__ x,
                    const int* __restrict__ kp,
                    float* __restrict__ out, int n) {
    const int row  = blockIdx.x;
    const int t    = threadIdx.x;
    const int lane = t & 31;
    const int wid  = t >> 5;
    constexpr int NK = EPV * 4;

    __shared__ Sm s;

    // Zero histogram: two uint4 stores per thread (2048 bins)
    ((uint4*)s.u.hist)[t]           = make_uint4(0, 0, 0, 0);
    ((uint4*)s.u.hist)[t + THREADS] = make_uint4(0, 0, 0, 0);

    const float4* xrow = (const float4*)(x + (size_t)row * n);
    const float4* bfv  = (const float4*)g_bf;

    float4 xv[EPV];     // x stays in registers (exact passthrough output)
    float  b[NK];       // boosted values; raw bits are monotone for positives
    #pragma unroll
    for (int j = 0; j < EPV; j++) {
        int f = t + j * THREADS;
        xv[j] = xrow[f];
        float4 bf = bfv[f];
        b[j*4+0] = xv[j].x * bf.x;
        b[j*4+1] = xv[j].y * bf.y;
        b[j*4+2] = xv[j].z * bf.z;
        b[j*4+3] = xv[j].w * bf.w;
    }
    if (t == 0) { s.sNum = 0; s.sCnt = 0xFFFFFFFFu; }
    __syncthreads();   // hist zeroed

    // Histogram positive values (sign bit clear): bin = float bits [30:20].
    // Plain conditional atomics — digits spread over ~80 hot bins, conflict
    // degree is low; aggregation machinery costs more than it saves (R7/R10).
    #pragma unroll
    for (int e = 0; e < NK; e++) {
        unsigned u = __float_as_uint(b[e]);
        if ((int)u >= 0)                         // positive or +0
            atomicAdd(&s.u.hist[u >> 20], 1u);   // u>>20 in [0,2047]
    }
    __syncthreads();

    const unsigned k0 = (unsigned)__ldg(kp);

    // Suffix-count scan; thread t owns bins [8t, 8t+8), kept in registers
    uint4 a4 = ((const uint4*)s.u.hist)[t * 2];
    uint4 b4 = ((const uint4*)s.u.hist)[t * 2 + 1];
    unsigned hh[BPT] = {a4.x, a4.y, a4.z, a4.w, b4.x, b4.y, b4.z, b4.w};
    unsigned tot = 0;
    #pragma unroll
    for (int i = 0; i < BPT; i++) tot += hh[i];

    unsigned v = tot;   // becomes sum over lanes [lane..31]
    #pragma unroll
    for (int off = 1; off < 32; off <<= 1) {
        unsigned u = __shfl_down_sync(0xFFFFFFFFu, v, off);
        if (lane + off < 32) v += u;
    }
    if (lane == 0) s.wtot[wid] = v;
    __syncthreads();

    unsigned run = v - tot;                 // in-warp suffix above own chunk
    for (int j = wid + 1; j < NWARP; j++)   // higher warps (broadcast reads)
        run += s.wtot[j];
    #pragma unroll
    for (int i = BPT - 1; i >= 0; i--) {
        unsigned nxt = run;      // suffix(bin+1)
        run += hh[i];            // suffix(bin)
        if (run >= k0 && nxt < k0) {   // unique crossing bin
            s.sBin = (unsigned)(t * BPT + i);
            s.sKr  = k0 - nxt;
            s.sCnt = hh[i];
        }
    }
    __syncthreads();
    const unsigned bin = s.sBin;
    const unsigned kr  = s.sKr;
    const unsigned C1  = s.sCnt;   // 0xFFFFFFFF if positives < k0

    float thresh;
    if (C1 <= CAP) {
        // Compact crossing-bin candidates: plain conditional atomic (rare).
        #pragma unroll
        for (int e = 0; e < NK; e++) {
            unsigned u = __float_as_uint(b[e]);
            if ((u >> 20) == bin)   // negatives can't match (bin < 2048)
                s.u.list[atomicAdd(&s.sNum, 1u)] = u;
        }
        __syncthreads();
        const unsigned C = s.sNum;   // == C1

        // Parallel rank on raw bits (uint order == float order for positives):
        // candidate with (gt < kr <= ge) is the kr-th largest in the bin.
        for (unsigned i = t; i < C; i += THREADS) {
            unsigned ki = s.u.list[i];
            unsigned gt = 0, ge = 0;
            #pragma unroll 4
            for (unsigned j = 0; j < C; j++) {
                unsigned lj = s.u.list[j];
                gt += (lj > ki)  ? 1u : 0u;
                ge += (lj >= ki) ? 1u : 0u;
            }
            if (gt < kr && ge >= kr) s.sThr = ki;   // ties write same value
        }
        __syncthreads();
        thresh = __uint_as_float(s.sThr);
    } else {
        // Exactness fallback (positives < k0): block-wide greedy bit-descent
        // over full monotone keys. Never taken on benchmark data.
        unsigned thr = 0;
        for (int bb = 31; bb >= 0; bb--) {
            unsigned test = thr | (1u << bb);
            unsigned c = 0;
            #pragma unroll
            for (int e = 0; e < NK; e++) c += (f2key(b[e]) >= test) ? 1u : 0u;
            c = __reduce_add_sync(0xFFFFFFFFu, c);
            if (lane == 0) s.wtot[wid] = c;
            __syncthreads();
            unsigned cb = 0;
            #pragma unroll
            for (int j = 0; j < NWARP; j++) cb += s.wtot[j];
            if (cb >= k0) thr = test;
            __syncthreads();
        }
        thresh = key2f(thr);
    }

    // Output: EXACT passthrough of register-resident x; float >= mask
    // (identical semantics to the reference's boosted >= bottom).
    float4* orow = (float4*)(out + (size_t)row * n);
    #pragma unroll
    for (int j = 0; j < EPV; j++) {
        int f = t + j * THREADS;
        float4 o;
        o.x = (b[j*4+0] >= thresh) ? xv[j].x : 0.0f;
        o.y = (b[j*4+1] >= thresh) ? xv[j].y : 0.0f;
        o.z = (b[j*4+2] >= thresh) ? xv[j].z : 0.0f;
        o.w = (b[j*4+3] >= thresh) ? xv[j].w : 0.0f;
        orow[f] = o;
    }
}

extern "C" void kernel_launch(void* const* d_in, const int* in_sizes, int n_in,
                              void* d_out, int out_size) {
    const float* x    = (const float*)d_in[0];
    const float* duty = (const float*)d_in[1];
    const int*   kp   = (const int*)d_in[2];
    float*       out  = (float*)d_out;

    int n    = in_sizes[1];          // 4096
    int rows = in_sizes[0] / n;      // 8192

    boost_kernel<<<(n + 255) / 256, 256>>>(duty, kp, n);

    int epv = n / (THREADS * 4);
    switch (epv) {
        case 1:  kwinner_kernel<1><<<rows, THREADS>>>(x, kp, out, n);  break;
        case 2:  kwinner_kernel<2><<<rows, THREADS>>>(x, kp, out, n);  break;
        case 4:  kwinner_kernel<4><<<rows, THREADS>>>(x, kp, out, n);  break;
        case 8:  kwinner_kernel<8><<<rows, THREADS>>>(x, kp, out, n);  break;
        case 16: kwinner_kernel<16><<<rows, THREADS>>>(x, kp, out, n); break;
        default: break; // unsupported shape (not expected for this problem)
    }
}